// round 3
// baseline (speedup 1.0000x reference)
#include <cuda_runtime.h>
#include <cuda_bf16.h>
#include <math.h>

// Problem constants
#define B_    8
#define N_    128
#define K_    16
#define ALPHA 0.01f
#define LAM   1.0f
#define KAPPA 1.0f
#define EPS   1e-6f

#define NODES (B_ * N_)   // 1024
#define STR   20          // shared column stride (floats): 80B, 16B-aligned, 2-way banks

// Scratch (device globals — no allocation allowed)
// M_g layout per node: [l4][k][c] so float4 idx (node*64 + l4*16 + k) is lane-coalesced.
__device__ __align__(16) float E_g[NODES * K_ * K_];
__device__ __align__(16) float M_g[NODES * K_ * K_];
__device__ __align__(16) float u_g[NODES * K_];

// ---------------------------------------------------------------------------
// Kernel 1: per-node precompute.  E = expm(A), A = phi.G (antisymmetric)
// Taylor-9 via even/odd split:  exp(A) = Pe(A2) + A*Po(A2)
//   Pe = I + A2/2 + A4/24 + A4*(A2/720 + A4/40320)
//   Po = I + A2/6 + A4/120 + A4*(A2/5040 + A4/362880)
// scaling-and-squaring with theta = 1.0 (inf-norm).
// All matrices column-major in shared (stride STR) -> columns are 4x LDS.128.
// Fixed multiplier rows cached in registers.
// ---------------------------------------------------------------------------
__global__ __launch_bounds__(256, 4)
void prep_kernel(const float* __restrict__ mu_q,
                 const float* __restrict__ sigma_q,
                 const float* __restrict__ phi,
                 const float* __restrict__ gen)
{
    const int node = blockIdx.x;
    const int tid  = threadIdx.x;          // 0..255
    const int r = tid >> 4, c = tid & 15;

    __shared__ __align__(16) float Acm [16 * STR];
    __shared__ __align__(16) float A2cm[16 * STR];
    __shared__ __align__(16) float A4cm[16 * STR];
    __shared__ __align__(16) float Xcm [16 * STR];
    __shared__ __align__(16) float Ycm [16 * STR];
    __shared__ float rowsum[16];
    __shared__ int   s_shift_sh;
    __shared__ float dinv[16];
    __shared__ float mush[16];

    const float p0 = __ldg(&phi[node*3 + 0]);
    const float p1 = __ldg(&phi[node*3 + 1]);
    const float p2 = __ldg(&phi[node*3 + 2]);
    const float a_raw = p0 * __ldg(&gen[tid])
                      + p1 * __ldg(&gen[256 + tid])
                      + p2 * __ldg(&gen[512 + tid]);
    Acm[c*STR + r] = a_raw;                 // column-major
    if (tid < 16) {
        const float sq = fmaxf(__ldg(&sigma_q[node*16 + tid]), EPS);
        dinv[tid] = 1.0f / (sq + EPS);
        mush[tid] = __ldg(&mu_q[node*16 + tid]);
    }
    __syncthreads();

    // inf-norm: row t = { Acm[l*STR + t] : l }
    if (tid < 16) {
        float s = 0.f;
        #pragma unroll
        for (int l = 0; l < 16; l++) s += fabsf(Acm[l*STR + tid]);
        rowsum[tid] = s;
    }
    __syncthreads();
    if (tid == 0) {
        float nrm = 0.f;
        #pragma unroll
        for (int l = 0; l < 16; l++) nrm = fmaxf(nrm, rowsum[l]);
        int s = 0;
        while (nrm > 1.0f && s < 30) { nrm *= 0.5f; s++; }
        s_shift_sh = s;
    }
    __syncthreads();
    const int   s_sq  = s_shift_sh;
    const float scale = ldexpf(1.0f, -s_sq);
    Acm[c*STR + r] = a_raw * scale;
    __syncthreads();

    // cache own row of A:  A[r][l] = Acm[l*STR + r]
    float arow[16];
    #pragma unroll
    for (int l = 0; l < 16; l++) arow[l] = Acm[l*STR + r];

    // ---- A2 = A*A : col c of A via LDS.128 ----
    float col[16];
    {
        const float4* p = (const float4*)(Acm + c*STR);
        float4 v0 = p[0], v1 = p[1], v2 = p[2], v3 = p[3];
        col[0]=v0.x; col[1]=v0.y; col[2]=v0.z; col[3]=v0.w;
        col[4]=v1.x; col[5]=v1.y; col[6]=v1.z; col[7]=v1.w;
        col[8]=v2.x; col[9]=v2.y; col[10]=v2.z; col[11]=v2.w;
        col[12]=v3.x; col[13]=v3.y; col[14]=v3.z; col[15]=v3.w;
    }
    float acc = 0.f;
    #pragma unroll
    for (int l = 0; l < 16; l++) acc = fmaf(arow[l], col[l], acc);
    A2cm[c*STR + r] = acc;
    __syncthreads();

    // ---- A4 = A2*A2 ----
    float a2row[16];
    #pragma unroll
    for (int l = 0; l < 16; l++) a2row[l] = A2cm[l*STR + r];
    {
        const float4* p = (const float4*)(A2cm + c*STR);
        float4 v0 = p[0], v1 = p[1], v2 = p[2], v3 = p[3];
        col[0]=v0.x; col[1]=v0.y; col[2]=v0.z; col[3]=v0.w;
        col[4]=v1.x; col[5]=v1.y; col[6]=v1.z; col[7]=v1.w;
        col[8]=v2.x; col[9]=v2.y; col[10]=v2.z; col[11]=v2.w;
        col[12]=v3.x; col[13]=v3.y; col[14]=v3.z; col[15]=v3.w;
    }
    acc = 0.f;
    #pragma unroll
    for (int l = 0; l < 16; l++) acc = fmaf(a2row[l], col[l], acc);
    A4cm[c*STR + r] = acc;
    __syncthreads();

    // ---- even/odd tails:  t_we = (A4*(A2/720 + A4/40320))[r][c], etc. ----
    float a4row[16];
    #pragma unroll
    for (int l = 0; l < 16; l++) a4row[l] = A4cm[l*STR + r];
    float colA2[16], colA4[16];
    {
        const float4* p = (const float4*)(A2cm + c*STR);
        float4 v0 = p[0], v1 = p[1], v2 = p[2], v3 = p[3];
        colA2[0]=v0.x; colA2[1]=v0.y; colA2[2]=v0.z; colA2[3]=v0.w;
        colA2[4]=v1.x; colA2[5]=v1.y; colA2[6]=v1.z; colA2[7]=v1.w;
        colA2[8]=v2.x; colA2[9]=v2.y; colA2[10]=v2.z; colA2[11]=v2.w;
        colA2[12]=v3.x; colA2[13]=v3.y; colA2[14]=v3.z; colA2[15]=v3.w;
        const float4* q = (const float4*)(A4cm + c*STR);
        float4 w0 = q[0], w1 = q[1], w2 = q[2], w3 = q[3];
        colA4[0]=w0.x; colA4[1]=w0.y; colA4[2]=w0.z; colA4[3]=w0.w;
        colA4[4]=w1.x; colA4[5]=w1.y; colA4[6]=w1.z; colA4[7]=w1.w;
        colA4[8]=w2.x; colA4[9]=w2.y; colA4[10]=w2.z; colA4[11]=w2.w;
        colA4[12]=w3.x; colA4[13]=w3.y; colA4[14]=w3.z; colA4[15]=w3.w;
    }
    float t_we = 0.f, t_wo = 0.f;
    #pragma unroll
    for (int l = 0; l < 16; l++) {
        t_we = fmaf(a4row[l], fmaf(colA2[l], 1.0f/720.0f,  colA4[l] * (1.0f/40320.0f)),  t_we);
        t_wo = fmaf(a4row[l], fmaf(colA2[l], 1.0f/5040.0f, colA4[l] * (1.0f/362880.0f)), t_wo);
    }
    const float A2rc = A2cm[c*STR + r];
    const float A4rc = A4cm[c*STR + r];
    const float idn  = (r == c) ? 1.0f : 0.0f;
    const float even = idn + 0.5f        * A2rc + (1.0f/24.0f)  * A4rc + t_we;
    const float oddv = idn + (1.0f/6.0f) * A2rc + (1.0f/120.0f) * A4rc + t_wo;
    Ycm[c*STR + r] = oddv;               // odd inner poly (temp in Ycm)
    __syncthreads();

    // ---- E = even + A * odd ----
    {
        const float4* p = (const float4*)(Ycm + c*STR);
        float4 v0 = p[0], v1 = p[1], v2 = p[2], v3 = p[3];
        col[0]=v0.x; col[1]=v0.y; col[2]=v0.z; col[3]=v0.w;
        col[4]=v1.x; col[5]=v1.y; col[6]=v1.z; col[7]=v1.w;
        col[8]=v2.x; col[9]=v2.y; col[10]=v2.z; col[11]=v2.w;
        col[12]=v3.x; col[13]=v3.y; col[14]=v3.z; col[15]=v3.w;
    }
    acc = even;
    #pragma unroll
    for (int l = 0; l < 16; l++) acc = fmaf(arow[l], col[l], acc);
    Xcm[c*STR + r] = acc;
    __syncthreads();

    // ---- squarings ----
    float* Xp = Xcm;
    float* Yp = Ycm;
    for (int t = 0; t < s_sq; t++) {
        float xrow[16];
        #pragma unroll
        for (int l = 0; l < 16; l++) xrow[l] = Xp[l*STR + r];
        {
            const float4* p = (const float4*)(Xp + c*STR);
            float4 v0 = p[0], v1 = p[1], v2 = p[2], v3 = p[3];
            col[0]=v0.x; col[1]=v0.y; col[2]=v0.z; col[3]=v0.w;
            col[4]=v1.x; col[5]=v1.y; col[6]=v1.z; col[7]=v1.w;
            col[8]=v2.x; col[9]=v2.y; col[10]=v2.z; col[11]=v2.w;
            col[12]=v3.x; col[13]=v3.y; col[14]=v3.z; col[15]=v3.w;
        }
        float s = 0.f;
        #pragma unroll
        for (int l = 0; l < 16; l++) s = fmaf(xrow[l], col[l], s);
        Yp[c*STR + r] = s;
        __syncthreads();
        float* tmp = Xp; Xp = Yp; Yp = tmp;
    }
    // Xp holds E, column-major.

    // ---- outputs ----
    // M[r][c] = sum_l E[l][r] * dinv[l] * E[l][c]  (cols r and c of E)
    {
        float colr[16], colc[16];
        const float4* p = (const float4*)(Xp + r*STR);
        float4 v0 = p[0], v1 = p[1], v2 = p[2], v3 = p[3];
        colr[0]=v0.x; colr[1]=v0.y; colr[2]=v0.z; colr[3]=v0.w;
        colr[4]=v1.x; colr[5]=v1.y; colr[6]=v1.z; colr[7]=v1.w;
        colr[8]=v2.x; colr[9]=v2.y; colr[10]=v2.z; colr[11]=v2.w;
        colr[12]=v3.x; colr[13]=v3.y; colr[14]=v3.z; colr[15]=v3.w;
        const float4* q = (const float4*)(Xp + c*STR);
        float4 w0 = q[0], w1 = q[1], w2 = q[2], w3 = q[3];
        colc[0]=w0.x; colc[1]=w0.y; colc[2]=w0.z; colc[3]=w0.w;
        colc[4]=w1.x; colc[5]=w1.y; colc[6]=w1.z; colc[7]=w1.w;
        colc[8]=w2.x; colc[9]=w2.y; colc[10]=w2.z; colc[11]=w2.w;
        colc[12]=w3.x; colc[13]=w3.y; colc[14]=w3.z; colc[15]=w3.w;
        float m = 0.f;
        #pragma unroll
        for (int l = 0; l < 16; l++) m = fmaf(colr[l] * dinv[l], colc[l], m);
        M_g[node*256 + (c >> 2)*64 + r*4 + (c & 3)] = m;   // permuted layout
        E_g[node*256 + r*16 + c] = Xp[c*STR + r];
    }
    // u[k] = col k of E  .  mu
    if (tid < 16) {
        float uu = 0.f;
        #pragma unroll
        for (int l = 0; l < 16; l++) uu = fmaf(Xp[tid*STR + l], mush[l], uu);
        u_g[node*16 + tid] = uu;
    }
}

// ---------------------------------------------------------------------------
// Kernel 2: pair reduction (unchanged from R2 win).
// ---------------------------------------------------------------------------
__global__ __launch_bounds__(128, 8)
void pair_kernel(const float* __restrict__ mu_q,
                 const float* __restrict__ sigma_q,
                 const float* __restrict__ mu_p,
                 const float* __restrict__ sigma_p,
                 const float* __restrict__ beta,
                 float* __restrict__ out)
{
    const int blk = blockIdx.x;
    const int b   = blk >> 7;
    const int i   = blk & 127;
    const int tid = threadIdx.x;       // 0..127

    __shared__ __align__(16) float u_sh[N_ * K_];    // 8 KB
    __shared__ float beta_sh[N_];
    __shared__ float red1[8][16];
    __shared__ float red2[8][16];
    __shared__ float red3[8];
    __shared__ float t_sh[16];

    float4* u_sh4 = (float4*)u_sh;
    const float4* ub4 = (const float4*)(u_g + b * N_ * K_);
    #pragma unroll
    for (int idx = tid; idx < N_ * K_ / 4; idx += 128) u_sh4[idx] = ub4[idx];
    beta_sh[tid] = __ldg(&beta[(b * N_ + i) * N_ + tid]);
    __syncthreads();

    const int k  = tid & 15;           // component / row
    const int hw = tid >> 4;           // half-warp id 0..7

    const float4 ui0 = u_sh4[i*4 + 0];
    const float4 ui1 = u_sh4[i*4 + 1];
    const float4 ui2 = u_sh4[i*4 + 2];
    const float4 ui3 = u_sh4[i*4 + 3];
    const float  ui_k = u_sh[i*16 + k];

    float s1 = 0.f, s2 = 0.f, s3 = 0.f;
    const float4* Mb4 = (const float4*)(M_g + b * N_ * 256);

    #pragma unroll 2
    for (int iter = 0; iter < 16; iter++) {
        const int j = iter * 8 + hw;
        const float4* Mj = Mb4 + j * 64;

        const float4 m0 = __ldg(&Mj[ 0 + k]);
        const float4 m1 = __ldg(&Mj[16 + k]);
        const float4 m2 = __ldg(&Mj[32 + k]);
        const float4 m3 = __ldg(&Mj[48 + k]);

        const float4 uj0 = u_sh4[j*4 + 0];
        const float4 uj1 = u_sh4[j*4 + 1];
        const float4 uj2 = u_sh4[j*4 + 2];
        const float4 uj3 = u_sh4[j*4 + 3];

        float4 w0, w1, w2, w3;
        w0.x = ui0.x - uj0.x; w0.y = ui0.y - uj0.y; w0.z = ui0.z - uj0.z; w0.w = ui0.w - uj0.w;
        w1.x = ui1.x - uj1.x; w1.y = ui1.y - uj1.y; w1.z = ui1.z - uj1.z; w1.w = ui1.w - uj1.w;
        w2.x = ui2.x - uj2.x; w2.y = ui2.y - uj2.y; w2.z = ui2.z - uj2.z; w2.w = ui2.w - uj2.w;
        w3.x = ui3.x - uj3.x; w3.y = ui3.y - uj3.y; w3.z = ui3.z - uj3.z; w3.w = ui3.w - uj3.w;

        float v = m0.x * w0.x;
        v = fmaf(m0.y, w0.y, v); v = fmaf(m0.z, w0.z, v); v = fmaf(m0.w, w0.w, v);
        v = fmaf(m1.x, w1.x, v); v = fmaf(m1.y, w1.y, v); v = fmaf(m1.z, w1.z, v); v = fmaf(m1.w, w1.w, v);
        v = fmaf(m2.x, w2.x, v); v = fmaf(m2.y, w2.y, v); v = fmaf(m2.z, w2.z, v); v = fmaf(m2.w, w2.w, v);
        v = fmaf(m3.x, w3.x, v); v = fmaf(m3.y, w3.y, v); v = fmaf(m3.z, w3.z, v); v = fmaf(m3.w, w3.w, v);

        const float wk = ui_k - u_sh[j*16 + k];
        float p = wk * v;
        p += __shfl_xor_sync(0xffffffffu, p, 8);
        p += __shfl_xor_sync(0xffffffffu, p, 4);
        p += __shfl_xor_sync(0xffffffffu, p, 2);
        p += __shfl_xor_sync(0xffffffffu, p, 1);
        const float kl = 0.5f * p;

        const float bj  = beta_sh[j];
        const float bkl = bj * kl;
        s1 = fmaf(bj,  v, s1);
        s2 = fmaf(bkl, v, s2);
        s3 += bkl;
    }

    red1[hw][k] = s1;
    red2[hw][k] = s2;
    if (k == 0) red3[hw] = s3;
    __syncthreads();

    if (tid < 16) {
        float S1 = 0.f, S2 = 0.f, S3 = 0.f;
        #pragma unroll
        for (int h = 0; h < 8; h++) {
            S1 += red1[h][tid];
            S2 += red2[h][tid];
            S3 += red3[h];
        }
        t_sh[tid] = LAM * S1 + (LAM / KAPPA) * (S2 - S3 * S1);
    }
    __syncthreads();

    if (tid < 16) {
        const int node = b * N_ + i;
        const float* Ei = E_g + node * 256;
        float g = 0.f;
        #pragma unroll
        for (int l = 0; l < 16; l++) g += Ei[tid*16 + l] * t_sh[l];

        const float sp = fmaxf(__ldg(&sigma_p[node*16 + tid]), EPS);
        const float sq = fmaxf(__ldg(&sigma_q[node*16 + tid]), EPS);
        const float dm = __ldg(&mu_q[node*16 + tid]) - __ldg(&mu_p[node*16 + tid]);

        out[node*16 + tid]                 = g + ALPHA * dm / sp;
        out[NODES*K_ + node*16 + tid]      = ALPHA * 0.5f * (1.0f / sp - 1.0f / sq);
    }
}

extern "C" void kernel_launch(void* const* d_in, const int* in_sizes, int n_in,
                              void* d_out, int out_size)
{
    const float* mu_q    = (const float*)d_in[0];
    const float* sigma_q = (const float*)d_in[1];
    const float* mu_p    = (const float*)d_in[2];
    const float* sigma_p = (const float*)d_in[3];
    const float* beta    = (const float*)d_in[4];
    const float* phi     = (const float*)d_in[5];
    const float* gen     = (const float*)d_in[6];
    float* out = (float*)d_out;

    prep_kernel<<<NODES, 256>>>(mu_q, sigma_q, phi, gen);
    pair_kernel<<<NODES, 128>>>(mu_q, sigma_q, mu_p, sigma_p, beta, out);
}

// round 4
// speedup vs baseline: 1.2528x; 1.2528x over previous
#include <cuda_runtime.h>
#include <cuda_bf16.h>
#include <math.h>

// Problem constants
#define B_    8
#define N_    128
#define K_    16
#define ALPHA 0.01f
#define LAM   1.0f
#define KAPPA 1.0f
#define EPS   1e-6f

#define NODES (B_ * N_)   // 1024
#define STR   20          // shared column stride (floats)

// Scratch (device globals — no allocation allowed)
// M_g layout per node: [l4][k][c] so float4 idx (node*64 + l4*16 + k) is lane-coalesced.
__device__ __align__(16) float E_g[NODES * K_ * K_];
__device__ __align__(16) float M_g[NODES * K_ * K_];
__device__ __align__(16) float u_g[NODES * K_];

// load a 16-float column (col-major, stride STR, 16B aligned) as 4x float4
#define LOADCOL(dst, base)                                            \
    {   const float4* _p = (const float4*)(base);                     \
        float4 _v0 = _p[0], _v1 = _p[1], _v2 = _p[2], _v3 = _p[3];    \
        dst[0]=_v0.x; dst[1]=_v0.y; dst[2]=_v0.z; dst[3]=_v0.w;       \
        dst[4]=_v1.x; dst[5]=_v1.y; dst[6]=_v1.z; dst[7]=_v1.w;       \
        dst[8]=_v2.x; dst[9]=_v2.y; dst[10]=_v2.z; dst[11]=_v2.w;     \
        dst[12]=_v3.x; dst[13]=_v3.y; dst[14]=_v3.z; dst[15]=_v3.w; }

// ---------------------------------------------------------------------------
// Kernel 1: per-node precompute.  E = expm(A), A = phi.G (antisymmetric)
// exp(A) = Pe(A2) + A*Po(A2), Taylor-9, scaling/squaring theta=1.0.
// Register-disciplined: one row + one streamed column live per phase.
// ---------------------------------------------------------------------------
__global__ __launch_bounds__(256)
void prep_kernel(const float* __restrict__ mu_q,
                 const float* __restrict__ sigma_q,
                 const float* __restrict__ phi,
                 const float* __restrict__ gen)
{
    const int node = blockIdx.x;
    const int tid  = threadIdx.x;          // 0..255
    const int r = tid >> 4, c = tid & 15;

    __shared__ __align__(16) float Acm [16 * STR];   // A
    __shared__ __align__(16) float Bcm [16 * STR];   // A2
    __shared__ __align__(16) float Ccm [16 * STR];   // A4
    __shared__ __align__(16) float Xcm [16 * STR];   // temp / ping
    __shared__ __align__(16) float Ycm [16 * STR];   // temp / pong
    __shared__ float rowsum[16];
    __shared__ int   s_shift_sh;
    __shared__ float dinv[16];
    __shared__ float mush[16];

    const float p0 = __ldg(&phi[node*3 + 0]);
    const float p1 = __ldg(&phi[node*3 + 1]);
    const float p2 = __ldg(&phi[node*3 + 2]);
    const float a_raw = p0 * __ldg(&gen[tid])
                      + p1 * __ldg(&gen[256 + tid])
                      + p2 * __ldg(&gen[512 + tid]);
    Acm[c*STR + r] = a_raw;                 // column-major
    if (tid < 16) {
        const float sq = fmaxf(__ldg(&sigma_q[node*16 + tid]), EPS);
        dinv[tid] = 1.0f / (sq + EPS);
        mush[tid] = __ldg(&mu_q[node*16 + tid]);
    }
    __syncthreads();

    if (tid < 16) {
        float s = 0.f;
        #pragma unroll
        for (int l = 0; l < 16; l++) s += fabsf(Acm[l*STR + tid]);
        rowsum[tid] = s;
    }
    __syncthreads();
    if (tid == 0) {
        float nrm = 0.f;
        #pragma unroll
        for (int l = 0; l < 16; l++) nrm = fmaxf(nrm, rowsum[l]);
        int s = 0;
        while (nrm > 1.0f && s < 30) { nrm *= 0.5f; s++; }
        s_shift_sh = s;
    }
    __syncthreads();
    const int   s_sq  = s_shift_sh;
    const float scale = ldexpf(1.0f, -s_sq);
    Acm[c*STR + r] = a_raw * scale;
    __syncthreads();

    // ---- A2 = A*A ----
    {
        float row[16], col[16];
        #pragma unroll
        for (int l = 0; l < 16; l++) row[l] = Acm[l*STR + r];
        LOADCOL(col, Acm + c*STR);
        float acc = 0.f;
        #pragma unroll
        for (int l = 0; l < 16; l++) acc = fmaf(row[l], col[l], acc);
        Bcm[c*STR + r] = acc;
    }
    __syncthreads();

    // ---- A4 = A2*A2 ----
    {
        float row[16], col[16];
        #pragma unroll
        for (int l = 0; l < 16; l++) row[l] = Bcm[l*STR + r];
        LOADCOL(col, Bcm + c*STR);
        float acc = 0.f;
        #pragma unroll
        for (int l = 0; l < 16; l++) acc = fmaf(row[l], col[l], acc);
        Ccm[c*STR + r] = acc;
    }
    __syncthreads();

    // ---- elementwise tail inputs: T -> Xcm, U -> Ycm ----
    {
        const float b = Bcm[c*STR + r];
        const float d = Ccm[c*STR + r];
        Xcm[c*STR + r] = b * (1.0f/720.0f)  + d * (1.0f/40320.0f);
        Ycm[c*STR + r] = b * (1.0f/5040.0f) + d * (1.0f/362880.0f);
    }
    __syncthreads();

    // ---- tails: t_we = (A4*T)[r][c], t_wo = (A4*U)[r][c] ----
    float even, oddv;
    {
        float row[16], col[16];
        #pragma unroll
        for (int l = 0; l < 16; l++) row[l] = Ccm[l*STR + r];
        LOADCOL(col, Xcm + c*STR);
        float t_we = 0.f;
        #pragma unroll
        for (int l = 0; l < 16; l++) t_we = fmaf(row[l], col[l], t_we);
        LOADCOL(col, Ycm + c*STR);
        float t_wo = 0.f;
        #pragma unroll
        for (int l = 0; l < 16; l++) t_wo = fmaf(row[l], col[l], t_wo);

        const float A2rc = Bcm[c*STR + r];
        const float A4rc = Ccm[c*STR + r];
        const float idn  = (r == c) ? 1.0f : 0.0f;
        even = idn + 0.5f        * A2rc + (1.0f/24.0f)  * A4rc + t_we;
        oddv = idn + (1.0f/6.0f) * A2rc + (1.0f/120.0f) * A4rc + t_wo;
    }
    __syncthreads();          // Xcm/Ycm reads done
    Xcm[c*STR + r] = oddv;    // odd poly -> Xcm
    __syncthreads();

    // ---- E = even + A * odd  -> Ycm ----
    {
        float row[16], col[16];
        #pragma unroll
        for (int l = 0; l < 16; l++) row[l] = Acm[l*STR + r];
        LOADCOL(col, Xcm + c*STR);
        float acc = even;
        #pragma unroll
        for (int l = 0; l < 16; l++) acc = fmaf(row[l], col[l], acc);
        Ycm[c*STR + r] = acc;
    }
    __syncthreads();

    // ---- squarings (ping-pong Ycm <-> Xcm) ----
    float* Xp = Ycm;
    float* Yp = Xcm;
    for (int t = 0; t < s_sq; t++) {
        float row[16], col[16];
        #pragma unroll
        for (int l = 0; l < 16; l++) row[l] = Xp[l*STR + r];
        LOADCOL(col, Xp + c*STR);
        float s = 0.f;
        #pragma unroll
        for (int l = 0; l < 16; l++) s = fmaf(row[l], col[l], s);
        Yp[c*STR + r] = s;
        __syncthreads();
        float* tmp = Xp; Xp = Yp; Yp = tmp;
    }
    // Xp holds E, column-major.

    // ---- M[r][c] = sum_l E[l][r] dinv[l] E[l][c] ----
    {
        float rowd[16], col[16];
        LOADCOL(rowd, Xp + r*STR);                 // col r of E
        #pragma unroll
        for (int l = 0; l < 16; l++) rowd[l] *= dinv[l];
        LOADCOL(col, Xp + c*STR);                  // col c of E
        float m = 0.f;
        #pragma unroll
        for (int l = 0; l < 16; l++) m = fmaf(rowd[l], col[l], m);
        M_g[node*256 + (c >> 2)*64 + r*4 + (c & 3)] = m;
        E_g[node*256 + r*16 + c] = Xp[c*STR + r];
    }
    if (tid < 16) {
        float uu = 0.f;
        #pragma unroll
        for (int l = 0; l < 16; l++) uu = fmaf(Xp[tid*STR + l], mush[l], uu);
        u_g[node*16 + tid] = uu;
    }
}

// ---------------------------------------------------------------------------
// Kernel 2: pair reduction (unchanged — protected R2 win).
// ---------------------------------------------------------------------------
__global__ __launch_bounds__(128, 8)
void pair_kernel(const float* __restrict__ mu_q,
                 const float* __restrict__ sigma_q,
                 const float* __restrict__ mu_p,
                 const float* __restrict__ sigma_p,
                 const float* __restrict__ beta,
                 float* __restrict__ out)
{
    const int blk = blockIdx.x;
    const int b   = blk >> 7;
    const int i   = blk & 127;
    const int tid = threadIdx.x;       // 0..127

    __shared__ __align__(16) float u_sh[N_ * K_];    // 8 KB
    __shared__ float beta_sh[N_];
    __shared__ float red1[8][16];
    __shared__ float red2[8][16];
    __shared__ float red3[8];
    __shared__ float t_sh[16];

    float4* u_sh4 = (float4*)u_sh;
    const float4* ub4 = (const float4*)(u_g + b * N_ * K_);
    #pragma unroll
    for (int idx = tid; idx < N_ * K_ / 4; idx += 128) u_sh4[idx] = ub4[idx];
    beta_sh[tid] = __ldg(&beta[(b * N_ + i) * N_ + tid]);
    __syncthreads();

    const int k  = tid & 15;           // component / row
    const int hw = tid >> 4;           // half-warp id 0..7

    const float4 ui0 = u_sh4[i*4 + 0];
    const float4 ui1 = u_sh4[i*4 + 1];
    const float4 ui2 = u_sh4[i*4 + 2];
    const float4 ui3 = u_sh4[i*4 + 3];
    const float  ui_k = u_sh[i*16 + k];

    float s1 = 0.f, s2 = 0.f, s3 = 0.f;
    const float4* Mb4 = (const float4*)(M_g + b * N_ * 256);

    #pragma unroll 2
    for (int iter = 0; iter < 16; iter++) {
        const int j = iter * 8 + hw;
        const float4* Mj = Mb4 + j * 64;

        const float4 m0 = __ldg(&Mj[ 0 + k]);
        const float4 m1 = __ldg(&Mj[16 + k]);
        const float4 m2 = __ldg(&Mj[32 + k]);
        const float4 m3 = __ldg(&Mj[48 + k]);

        const float4 uj0 = u_sh4[j*4 + 0];
        const float4 uj1 = u_sh4[j*4 + 1];
        const float4 uj2 = u_sh4[j*4 + 2];
        const float4 uj3 = u_sh4[j*4 + 3];

        float4 w0, w1, w2, w3;
        w0.x = ui0.x - uj0.x; w0.y = ui0.y - uj0.y; w0.z = ui0.z - uj0.z; w0.w = ui0.w - uj0.w;
        w1.x = ui1.x - uj1.x; w1.y = ui1.y - uj1.y; w1.z = ui1.z - uj1.z; w1.w = ui1.w - uj1.w;
        w2.x = ui2.x - uj2.x; w2.y = ui2.y - uj2.y; w2.z = ui2.z - uj2.z; w2.w = ui2.w - uj2.w;
        w3.x = ui3.x - uj3.x; w3.y = ui3.y - uj3.y; w3.z = ui3.z - uj3.z; w3.w = ui3.w - uj3.w;

        float v = m0.x * w0.x;
        v = fmaf(m0.y, w0.y, v); v = fmaf(m0.z, w0.z, v); v = fmaf(m0.w, w0.w, v);
        v = fmaf(m1.x, w1.x, v); v = fmaf(m1.y, w1.y, v); v = fmaf(m1.z, w1.z, v); v = fmaf(m1.w, w1.w, v);
        v = fmaf(m2.x, w2.x, v); v = fmaf(m2.y, w2.y, v); v = fmaf(m2.z, w2.z, v); v = fmaf(m2.w, w2.w, v);
        v = fmaf(m3.x, w3.x, v); v = fmaf(m3.y, w3.y, v); v = fmaf(m3.z, w3.z, v); v = fmaf(m3.w, w3.w, v);

        const float wk = ui_k - u_sh[j*16 + k];
        float p = wk * v;
        p += __shfl_xor_sync(0xffffffffu, p, 8);
        p += __shfl_xor_sync(0xffffffffu, p, 4);
        p += __shfl_xor_sync(0xffffffffu, p, 2);
        p += __shfl_xor_sync(0xffffffffu, p, 1);
        const float kl = 0.5f * p;

        const float bj  = beta_sh[j];
        const float bkl = bj * kl;
        s1 = fmaf(bj,  v, s1);
        s2 = fmaf(bkl, v, s2);
        s3 += bkl;
    }

    red1[hw][k] = s1;
    red2[hw][k] = s2;
    if (k == 0) red3[hw] = s3;
    __syncthreads();

    if (tid < 16) {
        float S1 = 0.f, S2 = 0.f, S3 = 0.f;
        #pragma unroll
        for (int h = 0; h < 8; h++) {
            S1 += red1[h][tid];
            S2 += red2[h][tid];
            S3 += red3[h];
        }
        t_sh[tid] = LAM * S1 + (LAM / KAPPA) * (S2 - S3 * S1);
    }
    __syncthreads();

    if (tid < 16) {
        const int node = b * N_ + i;
        const float* Ei = E_g + node * 256;
        float g = 0.f;
        #pragma unroll
        for (int l = 0; l < 16; l++) g += Ei[tid*16 + l] * t_sh[l];

        const float sp = fmaxf(__ldg(&sigma_p[node*16 + tid]), EPS);
        const float sq = fmaxf(__ldg(&sigma_q[node*16 + tid]), EPS);
        const float dm = __ldg(&mu_q[node*16 + tid]) - __ldg(&mu_p[node*16 + tid]);

        out[node*16 + tid]                 = g + ALPHA * dm / sp;
        out[NODES*K_ + node*16 + tid]      = ALPHA * 0.5f * (1.0f / sp - 1.0f / sq);
    }
}

extern "C" void kernel_launch(void* const* d_in, const int* in_sizes, int n_in,
                              void* d_out, int out_size)
{
    const float* mu_q    = (const float*)d_in[0];
    const float* sigma_q = (const float*)d_in[1];
    const float* mu_p    = (const float*)d_in[2];
    const float* sigma_p = (const float*)d_in[3];
    const float* beta    = (const float*)d_in[4];
    const float* phi     = (const float*)d_in[5];
    const float* gen     = (const float*)d_in[6];
    float* out = (float*)d_out;

    prep_kernel<<<NODES, 256>>>(mu_q, sigma_q, phi, gen);
    pair_kernel<<<NODES, 128>>>(mu_q, sigma_q, mu_p, sigma_p, beta, out);
}

// round 5
// speedup vs baseline: 1.4049x; 1.1213x over previous
#include <cuda_runtime.h>
#include <cuda_bf16.h>
#include <math.h>

// Problem constants
#define B_    8
#define N_    128
#define K_    16
#define ALPHA 0.01f
#define LAM   1.0f
#define KAPPA 1.0f
#define EPS   1e-6f

#define NODES (B_ * N_)   // 1024
#define STR   20          // shared column stride (floats)
#define IPB   4           // i-rows per block in pair_kernel

// Scratch (device globals — no allocation allowed)
// M_g layout per node: [l4][k][c] so float4 idx (node*64 + l4*16 + k) is lane-coalesced.
__device__ __align__(16) float E_g[NODES * K_ * K_];
__device__ __align__(16) float M_g[NODES * K_ * K_];
__device__ __align__(16) float u_g[NODES * K_];

// load a 16-float column (col-major, stride STR, 16B aligned) as 4x float4
#define LOADCOL(dst, base)                                            \
    {   const float4* _p = (const float4*)(base);                     \
        float4 _v0 = _p[0], _v1 = _p[1], _v2 = _p[2], _v3 = _p[3];    \
        dst[0]=_v0.x; dst[1]=_v0.y; dst[2]=_v0.z; dst[3]=_v0.w;       \
        dst[4]=_v1.x; dst[5]=_v1.y; dst[6]=_v1.z; dst[7]=_v1.w;       \
        dst[8]=_v2.x; dst[9]=_v2.y; dst[10]=_v2.z; dst[11]=_v2.w;     \
        dst[12]=_v3.x; dst[13]=_v3.y; dst[14]=_v3.z; dst[15]=_v3.w; }

// ---------------------------------------------------------------------------
// Kernel 1: per-node precompute.  E = expm(A), A = phi.G (antisymmetric)
// exp(A) = Pe(A2) + A*Po(A2), Taylor-9, scaling/squaring theta=1.0.
// Barrier-trimmed: shfl row-norm, tail poly folded into tail-dot phase.
// ---------------------------------------------------------------------------
__global__ __launch_bounds__(256)
void prep_kernel(const float* __restrict__ mu_q,
                 const float* __restrict__ sigma_q,
                 const float* __restrict__ phi,
                 const float* __restrict__ gen)
{
    const int node = blockIdx.x;
    const int tid  = threadIdx.x;          // 0..255
    const int r = tid >> 4, c = tid & 15;

    __shared__ __align__(16) float Acm [16 * STR];   // A (scaled)
    __shared__ __align__(16) float Bcm [16 * STR];   // A2
    __shared__ __align__(16) float Ccm [16 * STR];   // A4
    __shared__ __align__(16) float Xcm [16 * STR];   // temp / ping
    __shared__ __align__(16) float Ycm [16 * STR];   // temp / pong
    __shared__ float rowsum[16];
    __shared__ float dinv[16];
    __shared__ float mush[16];

    const float p0 = __ldg(&phi[node*3 + 0]);
    const float p1 = __ldg(&phi[node*3 + 1]);
    const float p2 = __ldg(&phi[node*3 + 2]);
    const float a_raw = p0 * __ldg(&gen[tid])
                      + p1 * __ldg(&gen[256 + tid])
                      + p2 * __ldg(&gen[512 + tid]);

    // row inf-norm via half-warp shfl over c (threads of one row are one half-warp)
    {
        float ab = fabsf(a_raw);
        ab += __shfl_xor_sync(0xffffffffu, ab, 8);
        ab += __shfl_xor_sync(0xffffffffu, ab, 4);
        ab += __shfl_xor_sync(0xffffffffu, ab, 2);
        ab += __shfl_xor_sync(0xffffffffu, ab, 1);
        if (c == 0) rowsum[r] = ab;
    }
    if (tid < 16) {
        const float sq = fmaxf(__ldg(&sigma_q[node*16 + tid]), EPS);
        dinv[tid] = 1.0f / (sq + EPS);
        mush[tid] = __ldg(&mu_q[node*16 + tid]);
    }
    __syncthreads();

    // every thread derives s identically (broadcast LDS; deterministic)
    int s_sq;
    {
        float nrm = 0.f;
        #pragma unroll
        for (int l = 0; l < 16; l++) nrm = fmaxf(nrm, rowsum[l]);
        int s = 0;
        while (nrm > 1.0f && s < 30) { nrm *= 0.5f; s++; }
        s_sq = s;
    }
    Acm[c*STR + r] = a_raw * ldexpf(1.0f, -s_sq);
    __syncthreads();

    // ---- A2 = A*A ----
    {
        float row[16], col[16];
        #pragma unroll
        for (int l = 0; l < 16; l++) row[l] = Acm[l*STR + r];
        LOADCOL(col, Acm + c*STR);
        float acc = 0.f;
        #pragma unroll
        for (int l = 0; l < 16; l++) acc = fmaf(row[l], col[l], acc);
        Bcm[c*STR + r] = acc;
    }
    __syncthreads();

    // ---- A4 = A2*A2 ----
    {
        float row[16], col[16];
        #pragma unroll
        for (int l = 0; l < 16; l++) row[l] = Bcm[l*STR + r];
        LOADCOL(col, Bcm + c*STR);
        float acc = 0.f;
        #pragma unroll
        for (int l = 0; l < 16; l++) acc = fmaf(row[l], col[l], acc);
        Ccm[c*STR + r] = acc;
    }
    __syncthreads();

    // ---- tails folded: t_we = (A4*(A2/720 + A4/40320))[r][c], etc. ----
    float even;
    {
        float row[16], colA2[16], colA4[16];
        #pragma unroll
        for (int l = 0; l < 16; l++) row[l] = Ccm[l*STR + r];
        LOADCOL(colA2, Bcm + c*STR);
        LOADCOL(colA4, Ccm + c*STR);
        float t_we = 0.f, t_wo = 0.f;
        #pragma unroll
        for (int l = 0; l < 16; l++) {
            t_we = fmaf(row[l], fmaf(colA2[l], 1.0f/720.0f,  colA4[l] * (1.0f/40320.0f)),  t_we);
            t_wo = fmaf(row[l], fmaf(colA2[l], 1.0f/5040.0f, colA4[l] * (1.0f/362880.0f)), t_wo);
        }
        const float A2rc = Bcm[c*STR + r];
        const float A4rc = Ccm[c*STR + r];
        const float idn  = (r == c) ? 1.0f : 0.0f;
        even = idn + 0.5f        * A2rc + (1.0f/24.0f)  * A4rc + t_we;
        Xcm[c*STR + r] = idn + (1.0f/6.0f) * A2rc + (1.0f/120.0f) * A4rc + t_wo;  // odd poly
    }
    __syncthreads();

    // ---- E = even + A * odd  -> Ycm ----
    {
        float row[16], col[16];
        #pragma unroll
        for (int l = 0; l < 16; l++) row[l] = Acm[l*STR + r];
        LOADCOL(col, Xcm + c*STR);
        float acc = even;
        #pragma unroll
        for (int l = 0; l < 16; l++) acc = fmaf(row[l], col[l], acc);
        Ycm[c*STR + r] = acc;
    }
    __syncthreads();

    // ---- squarings (ping-pong Ycm <-> Xcm) ----
    float* Xp = Ycm;
    float* Yp = Xcm;
    for (int t = 0; t < s_sq; t++) {
        float row[16], col[16];
        #pragma unroll
        for (int l = 0; l < 16; l++) row[l] = Xp[l*STR + r];
        LOADCOL(col, Xp + c*STR);
        float s = 0.f;
        #pragma unroll
        for (int l = 0; l < 16; l++) s = fmaf(row[l], col[l], s);
        Yp[c*STR + r] = s;
        __syncthreads();
        float* tmp = Xp; Xp = Yp; Yp = tmp;
    }
    // Xp holds E, column-major.

    // ---- M[r][c] = sum_l E[l][r] dinv[l] E[l][c] ----
    {
        float rowd[16], col[16];
        LOADCOL(rowd, Xp + r*STR);                 // col r of E
        #pragma unroll
        for (int l = 0; l < 16; l++) rowd[l] *= dinv[l];
        LOADCOL(col, Xp + c*STR);                  // col c of E
        float m = 0.f;
        #pragma unroll
        for (int l = 0; l < 16; l++) m = fmaf(rowd[l], col[l], m);
        M_g[node*256 + (c >> 2)*64 + r*4 + (c & 3)] = m;
        E_g[node*256 + r*16 + c] = Xp[c*STR + r];
    }
    if (tid < 16) {
        float uu = 0.f;
        #pragma unroll
        for (int l = 0; l < 16; l++) uu = fmaf(Xp[tid*STR + l], mush[l], uu);
        u_g[node*16 + tid] = uu;
    }
}

// ---------------------------------------------------------------------------
// Kernel 2: pair reduction, IPB=4 i-rows per block (M traffic amortized 4x).
// Grid = 256 blocks, 128 threads = 8 half-warps; hw owns j = iter*8+hw.
// Per j:  t_j = M_j u_j (once);  per i:  a = M_j u_i,  v = a - t_j,
//         kl = 0.5 w.v (shfl-16),  accumulate S1/S2/s3.
// ---------------------------------------------------------------------------
__global__ __launch_bounds__(128, 4)
void pair_kernel(const float* __restrict__ mu_q,
                 const float* __restrict__ sigma_q,
                 const float* __restrict__ mu_p,
                 const float* __restrict__ sigma_p,
                 const float* __restrict__ beta,
                 float* __restrict__ out)
{
    const int blk = blockIdx.x;        // 0..255
    const int b   = blk >> 5;          // 32 blocks per batch
    const int i0  = (blk & 31) * IPB;
    const int tid = threadIdx.x;       // 0..127

    __shared__ __align__(16) float u_sh[N_ * K_];     // 8 KB
    __shared__ float beta_sh[IPB][N_];
    __shared__ float red1[IPB][8][16];
    __shared__ float red2[IPB][8][16];
    __shared__ float red3[IPB][8];
    __shared__ float t_sh[IPB][16];

    float4* u_sh4 = (float4*)u_sh;
    const float4* ub4 = (const float4*)(u_g + b * N_ * K_);
    #pragma unroll
    for (int idx = tid; idx < N_ * K_ / 4; idx += 128) u_sh4[idx] = ub4[idx];
    #pragma unroll
    for (int ii = 0; ii < IPB; ii++)
        beta_sh[ii][tid] = __ldg(&beta[(b * N_ + i0 + ii) * N_ + tid]);
    __syncthreads();

    const int k  = tid & 15;           // component / row
    const int hw = tid >> 4;           // half-warp id 0..7

    // cache the 4 u_i vectors in registers (all static indices)
    float uir[IPB][16];
    float uik[IPB];
    #pragma unroll
    for (int ii = 0; ii < IPB; ii++) {
        const float4* p = (const float4*)(u_sh + (i0 + ii) * 16);
        float4 v0 = p[0], v1 = p[1], v2 = p[2], v3 = p[3];
        uir[ii][0]=v0.x;  uir[ii][1]=v0.y;  uir[ii][2]=v0.z;  uir[ii][3]=v0.w;
        uir[ii][4]=v1.x;  uir[ii][5]=v1.y;  uir[ii][6]=v1.z;  uir[ii][7]=v1.w;
        uir[ii][8]=v2.x;  uir[ii][9]=v2.y;  uir[ii][10]=v2.z; uir[ii][11]=v2.w;
        uir[ii][12]=v3.x; uir[ii][13]=v3.y; uir[ii][14]=v3.z; uir[ii][15]=v3.w;
        uik[ii] = u_sh[(i0 + ii) * 16 + k];
    }

    float s1[IPB], s2[IPB], s3[IPB];
    #pragma unroll
    for (int ii = 0; ii < IPB; ii++) { s1[ii]=0.f; s2[ii]=0.f; s3[ii]=0.f; }

    const float4* Mb4 = (const float4*)(M_g + b * N_ * 256);

    for (int iter = 0; iter < 16; iter++) {
        const int j = iter * 8 + hw;
        const float4* Mj = Mb4 + j * 64;

        const float4 m0 = __ldg(&Mj[ 0 + k]);
        const float4 m1 = __ldg(&Mj[16 + k]);
        const float4 m2 = __ldg(&Mj[32 + k]);
        const float4 m3 = __ldg(&Mj[48 + k]);

        const float4* up = (const float4*)(u_sh + j * 16);
        const float4 uj0 = up[0], uj1 = up[1], uj2 = up[2], uj3 = up[3];
        const float  ujk = u_sh[j * 16 + k];

        // t_j[k] = M_j[k][:] . u_j
        float tj = m0.x * uj0.x;
        tj = fmaf(m0.y, uj0.y, tj); tj = fmaf(m0.z, uj0.z, tj); tj = fmaf(m0.w, uj0.w, tj);
        tj = fmaf(m1.x, uj1.x, tj); tj = fmaf(m1.y, uj1.y, tj); tj = fmaf(m1.z, uj1.z, tj); tj = fmaf(m1.w, uj1.w, tj);
        tj = fmaf(m2.x, uj2.x, tj); tj = fmaf(m2.y, uj2.y, tj); tj = fmaf(m2.z, uj2.z, tj); tj = fmaf(m2.w, uj2.w, tj);
        tj = fmaf(m3.x, uj3.x, tj); tj = fmaf(m3.y, uj3.y, tj); tj = fmaf(m3.z, uj3.z, tj); tj = fmaf(m3.w, uj3.w, tj);

        #pragma unroll
        for (int ii = 0; ii < IPB; ii++) {
            float a = m0.x * uir[ii][0];
            a = fmaf(m0.y, uir[ii][1],  a); a = fmaf(m0.z, uir[ii][2],  a); a = fmaf(m0.w, uir[ii][3],  a);
            a = fmaf(m1.x, uir[ii][4],  a); a = fmaf(m1.y, uir[ii][5],  a); a = fmaf(m1.z, uir[ii][6],  a); a = fmaf(m1.w, uir[ii][7],  a);
            a = fmaf(m2.x, uir[ii][8],  a); a = fmaf(m2.y, uir[ii][9],  a); a = fmaf(m2.z, uir[ii][10], a); a = fmaf(m2.w, uir[ii][11], a);
            a = fmaf(m3.x, uir[ii][12], a); a = fmaf(m3.y, uir[ii][13], a); a = fmaf(m3.z, uir[ii][14], a); a = fmaf(m3.w, uir[ii][15], a);

            const float v = a - tj;
            const float w = uik[ii] - ujk;
            float p = w * v;
            p += __shfl_xor_sync(0xffffffffu, p, 8);
            p += __shfl_xor_sync(0xffffffffu, p, 4);
            p += __shfl_xor_sync(0xffffffffu, p, 2);
            p += __shfl_xor_sync(0xffffffffu, p, 1);
            const float kl = 0.5f * p;

            const float bj  = beta_sh[ii][j];
            const float bkl = bj * kl;
            s1[ii] = fmaf(bj,  v, s1[ii]);
            s2[ii] = fmaf(bkl, v, s2[ii]);
            s3[ii] += bkl;
        }
    }

    #pragma unroll
    for (int ii = 0; ii < IPB; ii++) {
        red1[ii][hw][k] = s1[ii];
        red2[ii][hw][k] = s2[ii];
        if (k == 0) red3[ii][hw] = s3[ii];
    }
    __syncthreads();

    if (tid < 16 * IPB) {
        const int ii = tid >> 4, kk = tid & 15;
        float S1 = 0.f, S2 = 0.f, S3 = 0.f;
        #pragma unroll
        for (int h = 0; h < 8; h++) {
            S1 += red1[ii][h][kk];
            S2 += red2[ii][h][kk];
            S3 += red3[ii][h];
        }
        t_sh[ii][kk] = LAM * S1 + (LAM / KAPPA) * (S2 - S3 * S1);
    }
    __syncthreads();

    if (tid < 16 * IPB) {
        const int ii = tid >> 4, kk = tid & 15;
        const int node = b * N_ + i0 + ii;
        const float* Ei = E_g + node * 256;
        float g = 0.f;
        #pragma unroll
        for (int l = 0; l < 16; l++) g = fmaf(Ei[kk*16 + l], t_sh[ii][l], g);

        const float sp = fmaxf(__ldg(&sigma_p[node*16 + kk]), EPS);
        const float sq = fmaxf(__ldg(&sigma_q[node*16 + kk]), EPS);
        const float dm = __ldg(&mu_q[node*16 + kk]) - __ldg(&mu_p[node*16 + kk]);

        out[node*16 + kk]            = g + ALPHA * dm / sp;
        out[NODES*K_ + node*16 + kk] = ALPHA * 0.5f * (1.0f / sp - 1.0f / sq);
    }
}

extern "C" void kernel_launch(void* const* d_in, const int* in_sizes, int n_in,
                              void* d_out, int out_size)
{
    const float* mu_q    = (const float*)d_in[0];
    const float* sigma_q = (const float*)d_in[1];
    const float* mu_p    = (const float*)d_in[2];
    const float* sigma_p = (const float*)d_in[3];
    const float* beta    = (const float*)d_in[4];
    const float* phi     = (const float*)d_in[5];
    const float* gen     = (const float*)d_in[6];
    float* out = (float*)d_out;

    prep_kernel<<<NODES, 256>>>(mu_q, sigma_q, phi, gen);
    pair_kernel<<<NODES / IPB, 128>>>(mu_q, sigma_q, mu_p, sigma_p, beta, out);
}